// round 14
// baseline (speedup 1.0000x reference)
#include <cuda_runtime.h>

// 2-layer LSTM (B=1024, T=512, I=1, H=64) + FC(64->1).
// 128 CTAs x 8 batches each, 128 threads/CTA, everything resident in SMEM.
// Matvecs use fma.rn.f32x2 (FFMA2) with 2 batches packed per register.

typedef unsigned long long u64;

#define NB 8
#define NCTA 128
#define NTHR 128
#define TLEN 512
#define HID  64
#define G4   256   // 4*H

// smem floats: W0T[64][256] + W1T[128][256] + xb[512][8] + v[128][8] + gb[4][256][2]
#define SMEM_FLOATS (64*256 + 128*256 + 512*8 + 128*8 + 4*256*2)
#define SMEM_BYTES  (SMEM_FLOATS * 4)

__device__ __forceinline__ u64 pk2(float a, float b) {
    u64 r;
    asm("mov.b64 %0,{%1,%2};" : "=l"(r) : "f"(a), "f"(b));
    return r;
}
__device__ __forceinline__ void fma2(u64 &d, u64 a, u64 b) {
    asm("fma.rn.f32x2 %0,%1,%2,%0;" : "+l"(d) : "l"(a), "l"(b));
}
__device__ __forceinline__ void lds128(u64 &a, u64 &b, unsigned addr) {
    asm volatile("ld.shared.v2.u64 {%0,%1},[%2];" : "=l"(a), "=l"(b) : "r"(addr));
}
__device__ __forceinline__ void sts128(unsigned addr, u64 a, u64 b) {
    asm volatile("st.shared.v2.u64 [%0],{%1,%2};" :: "r"(addr), "l"(a), "l"(b) : "memory");
}

__device__ __forceinline__ float sigm(float x) {
    return __fdividef(1.0f, 1.0f + __expf(-x));
}
__device__ __forceinline__ float tanh_(float x) {
    x = fminf(15.0f, fmaxf(-15.0f, x));
    float e = __expf(-2.0f * x);
    return __fdividef(1.0f - e, 1.0f + e);
}

__global__ void __launch_bounds__(NTHR, 1)
lstm2_kernel(const float* __restrict__ x,
             const float* __restrict__ Wih0, const float* __restrict__ Whh0,
             const float* __restrict__ bih0, const float* __restrict__ bhh0,
             const float* __restrict__ Wih1, const float* __restrict__ Whh1,
             const float* __restrict__ bih1, const float* __restrict__ bhh1,
             const float* __restrict__ Wfc,  const float* __restrict__ bfc,
             float* __restrict__ out)
{
    extern __shared__ float sm[];
    float* W0T = sm;                    // [64][256]   transposed Whh0
    float* W1T = W0T + 64 * 256;        // [128][256]  transposed [Wih1 ; Whh1]
    float* xb  = W1T + 128 * 256;       // [512][8]    x slice for this CTA's batches
    float* v   = xb + 512 * 8;          // [128][8]    rows 0..63: h0, rows 64..127: h1
    float* gb  = v + 128 * 8;           // [4 pairs][256 gates][2]  gate staging

    const int tid = threadIdx.x;
    const int b0  = blockIdx.x * NB;

    // ---- stage weights (transposed so matvec W-loads are lane-coalesced) ----
    for (int i = tid; i < 256 * 64; i += NTHR) {
        int j = i >> 6, k = i & 63;          // row j (gate), col k (hidden)
        W0T[k * 256 + j]        = Whh0[i];
        W1T[k * 256 + j]        = Wih1[i];
        W1T[(k + 64) * 256 + j] = Whh1[i];
    }
    // ---- stage x: xb[t][bb] ----
    for (int bb = 0; bb < NB; bb++) {
        const float* xr = x + (size_t)(b0 + bb) * TLEN;
        for (int t = tid; t < TLEN; t += NTHR) xb[t * 8 + bb] = xr[t];
    }
    // ---- zero state ----
    for (int i = tid; i < 128 * 8; i += NTHR) v[i] = 0.0f;

    // ---- per-thread constants (thread owns gates g0, g0+1) ----
    const int g0 = 2 * tid;
    const float bs0a = bih0[g0]     + bhh0[g0];
    const float bs0b = bih0[g0 + 1] + bhh0[g0 + 1];
    const float bs1a = bih1[g0]     + bhh1[g0];
    const float bs1b = bih1[g0 + 1] + bhh1[g0 + 1];
    const u64 bi0a = pk2(bs0a, bs0a), bi0b = pk2(bs0b, bs0b);
    const u64 bi1a = pk2(bs1a, bs1a), bi1b = pk2(bs1b, bs1b);
    const u64 wxa  = pk2(Wih0[g0], Wih0[g0]);
    const u64 wxb  = pk2(Wih0[g0 + 1], Wih0[g0 + 1]);

    const unsigned v_sa  = (unsigned)__cvta_generic_to_shared(v);
    const unsigned xb_sa = (unsigned)__cvta_generic_to_shared(xb);
    const unsigned gb_sa = (unsigned)__cvta_generic_to_shared(gb);
    const unsigned gst   = gb_sa + (unsigned)g0 * 8;   // +p*2048 per batch-pair

    // ---- update-phase assignment: thread -> (hidden unit u, 4 batches) ----
    const int u    = tid & 63;
    const int half = tid >> 6;                         // batches half*4 .. half*4+3
    float c0[4] = {0.f, 0.f, 0.f, 0.f};
    float c1[4] = {0.f, 0.f, 0.f, 0.f};

    __syncthreads();

    u64 a00, a01, a02, a03, a10, a11, a12, a13;

    for (int t = 0; t < TLEN; t++) {
        // ===== Phase A: layer-0 gates = bias + Wih0*x_t + Whh0 @ h0 =====
        {
            u64 x01, x23, x45, x67;
            lds128(x01, x23, xb_sa + (unsigned)t * 32);
            lds128(x45, x67, xb_sa + (unsigned)t * 32 + 16);
            a00 = bi0a; a01 = bi0a; a02 = bi0a; a03 = bi0a;
            a10 = bi0b; a11 = bi0b; a12 = bi0b; a13 = bi0b;
            fma2(a00, wxa, x01); fma2(a01, wxa, x23); fma2(a02, wxa, x45); fma2(a03, wxa, x67);
            fma2(a10, wxb, x01); fma2(a11, wxb, x23); fma2(a12, wxb, x45); fma2(a13, wxb, x67);
        }
        #pragma unroll 16
        for (int k = 0; k < HID; k++) {
            u64 h01, h23, h45, h67;
            lds128(h01, h23, v_sa + (unsigned)k * 32);        // broadcast (uniform addr)
            lds128(h45, h67, v_sa + (unsigned)k * 32 + 16);
            float2 w = *(const float2*)(W0T + k * 256 + g0);  // lane-coalesced LDS.64
            u64 wa = pk2(w.x, w.x), wb = pk2(w.y, w.y);
            fma2(a00, wa, h01); fma2(a01, wa, h23); fma2(a02, wa, h45); fma2(a03, wa, h67);
            fma2(a10, wb, h01); fma2(a11, wb, h23); fma2(a12, wb, h45); fma2(a13, wb, h67);
        }
        sts128(gst,        a00, a10);
        sts128(gst + 2048, a01, a11);
        sts128(gst + 4096, a02, a12);
        sts128(gst + 6144, a03, a13);
        __syncthreads();

        // ===== Phase B: layer-0 elementwise update -> h0 (v rows 0..63) =====
        #pragma unroll
        for (int q = 0; q < 4; q++) {
            int b = half * 4 + q;
            const float* gp = gb + (b >> 1) * 512 + (b & 1);
            float iv = gp[u * 2];
            float fv = gp[(u + 64) * 2];
            float gv = gp[(u + 128) * 2];
            float ov = gp[(u + 192) * 2];
            float c  = __fmaf_rn(sigm(fv), c0[q], sigm(iv) * tanh_(gv));
            c0[q] = c;
            v[u * 8 + b] = sigm(ov) * tanh_(c);
        }
        __syncthreads();

        // ===== Phase C: layer-1 gates = bias + [Wih1|Whh1] @ [h0_t ; h1_{t-1}] =====
        a00 = bi1a; a01 = bi1a; a02 = bi1a; a03 = bi1a;
        a10 = bi1b; a11 = bi1b; a12 = bi1b; a13 = bi1b;
        #pragma unroll 16
        for (int k = 0; k < 128; k++) {
            u64 h01, h23, h45, h67;
            lds128(h01, h23, v_sa + (unsigned)k * 32);
            lds128(h45, h67, v_sa + (unsigned)k * 32 + 16);
            float2 w = *(const float2*)(W1T + k * 256 + g0);
            u64 wa = pk2(w.x, w.x), wb = pk2(w.y, w.y);
            fma2(a00, wa, h01); fma2(a01, wa, h23); fma2(a02, wa, h45); fma2(a03, wa, h67);
            fma2(a10, wb, h01); fma2(a11, wb, h23); fma2(a12, wb, h45); fma2(a13, wb, h67);
        }
        sts128(gst,        a00, a10);
        sts128(gst + 2048, a01, a11);
        sts128(gst + 4096, a02, a12);
        sts128(gst + 6144, a03, a13);
        __syncthreads();

        // ===== Phase D: layer-1 elementwise update -> h1 (v rows 64..127) =====
        #pragma unroll
        for (int q = 0; q < 4; q++) {
            int b = half * 4 + q;
            const float* gp = gb + (b >> 1) * 512 + (b & 1);
            float iv = gp[u * 2];
            float fv = gp[(u + 64) * 2];
            float gv = gp[(u + 128) * 2];
            float ov = gp[(u + 192) * 2];
            float c  = __fmaf_rn(sigm(fv), c1[q], sigm(iv) * tanh_(gv));
            c1[q] = c;
            v[(64 + u) * 8 + b] = sigm(ov) * tanh_(c);
        }
        __syncthreads();
    }

    // ===== FC: out[b] = h1_last[b] . Wfc + bfc =====
    if (tid < NB) {
        float s = bfc[0];
        #pragma unroll 16
        for (int uu = 0; uu < HID; uu++)
            s = __fmaf_rn(Wfc[uu], v[(64 + uu) * 8 + tid], s);
        out[b0 + tid] = s;
    }
}

extern "C" void kernel_launch(void* const* d_in, const int* in_sizes, int n_in,
                              void* d_out, int out_size) {
    (void)in_sizes; (void)n_in; (void)out_size;
    const float* x    = (const float*)d_in[0];
    const float* Wih0 = (const float*)d_in[1];
    const float* Whh0 = (const float*)d_in[2];
    const float* bih0 = (const float*)d_in[3];
    const float* bhh0 = (const float*)d_in[4];
    const float* Wih1 = (const float*)d_in[5];
    const float* Whh1 = (const float*)d_in[6];
    const float* bih1 = (const float*)d_in[7];
    const float* bhh1 = (const float*)d_in[8];
    const float* Wfc  = (const float*)d_in[9];
    const float* bfc  = (const float*)d_in[10];
    float* out = (float*)d_out;

    cudaFuncSetAttribute(lstm2_kernel,
                         cudaFuncAttributeMaxDynamicSharedMemorySize, SMEM_BYTES);
    lstm2_kernel<<<NCTA, NTHR, SMEM_BYTES>>>(x, Wih0, Whh0, bih0, bhh0,
                                             Wih1, Whh1, bih1, bhh1,
                                             Wfc, bfc, out);
}